// round 6
// baseline (speedup 1.0000x reference)
#include <cuda_runtime.h>
#include <cuda_bf16.h>

#define Bsz 64
#define Lsz 1024
#define Dsz 1024
#define Csz 128          // NUM_CLASS + 2
#define STOPTAG 127

// ---------------- scratch (device globals; no allocation allowed) ----------------
__device__ float g_emis[(size_t)Bsz * Lsz * Csz];            // 32 MB
__device__ float g_scores[(size_t)Bsz * (Lsz + 1) * Csz];    // 33.6 MB
__device__ float g_Tt[Csz * Csz];                            // 64 KB transposed T
__device__ int   g_len[Bsz];
__device__ int   g_sel;      // which 65536-elem candidate is the mask (0=A,1=B)
__device__ int   g_width;    // mask element storage width in bytes (1,4,8)

// ---------------- identify the mask among the two 65536-elem inputs ----------------
// A prefix mask row 0 has all values in {0,1} (or f32 bits {0, 0x3F800000}).
// Labels y (0..125) fail every width hypothesis with overwhelming probability.
// Check widest-first so an int32/int64 mask isn't misread at a narrower width.
__global__ void detect_kernel(const unsigned char* A, const unsigned char* B) {
    __shared__ int bad[6];              // [cand*3 + w], w: 0=u64, 1=u32/f32, 2=u8
    int tid = threadIdx.x;
    if (tid < 6) bad[tid] = 0;
    __syncthreads();
    for (int cand = 0; cand < 2; ++cand) {
        const unsigned char* P = cand ? B : A;
        if (!P) { if (tid == 0) { bad[cand*3+0] = bad[cand*3+1] = bad[cand*3+2] = 1; } continue; }
        const unsigned long long* p8 = (const unsigned long long*)P;
        const unsigned* p4 = (const unsigned*)P;
        for (int i = tid; i < 1024; i += 256) {
            unsigned long long v8 = p8[i];
            if (v8 > 1ull) atomicOr(&bad[cand*3+0], 1);
            unsigned v4 = p4[i];
            if (v4 != 0u && v4 != 1u && v4 != 0x3F800000u) atomicOr(&bad[cand*3+1], 1);
            if (P[i] > 1) atomicOr(&bad[cand*3+2], 1);
        }
    }
    __syncthreads();
    if (tid == 0) {
        int sel = 0, width = 1;
        bool done = false;
        for (int cand = 0; cand < 2 && !done; ++cand) {
            if      (!bad[cand*3+0]) { sel = cand; width = 8; done = true; }
            else if (!bad[cand*3+1]) { sel = cand; width = 4; done = true; }
            else if (!bad[cand*3+2]) { sel = cand; width = 1; done = true; }
        }
        g_sel = sel; g_width = width;
    }
}

// ---------------- sequence lengths: count nonzero per row at detected width ----------------
__global__ void len_kernel(const unsigned char* A, const unsigned char* B) {
    const unsigned char* M = g_sel ? B : A;
    const int w = g_width;
    const int b = blockIdx.x, tid = threadIdx.x;
    int cnt = 0;
    if (w == 8) {
        const unsigned long long* p = ((const unsigned long long*)M) + (size_t)b * Lsz;
        for (int i = tid; i < Lsz; i += 256) cnt += (p[i] != 0ull) ? 1 : 0;
    } else if (w == 4) {
        const unsigned* p = ((const unsigned*)M) + (size_t)b * Lsz;
        for (int i = tid; i < Lsz; i += 256) cnt += (p[i] != 0u) ? 1 : 0;
    } else {
        const unsigned char* p = M + (size_t)b * Lsz;
        for (int i = tid; i < Lsz; i += 256) cnt += (p[i] != 0) ? 1 : 0;
    }
    #pragma unroll
    for (int off = 16; off; off >>= 1) cnt += __shfl_xor_sync(0xffffffffu, cnt, off);
    __shared__ int sr[8];
    if ((tid & 31) == 0) sr[tid >> 5] = cnt;
    __syncthreads();
    if (tid == 0) {
        int s = 0;
        #pragma unroll
        for (int i = 0; i < 8; ++i) s += sr[i];
        g_len[b] = s;
    }
}

// ---------------- transpose T: g_Tt[cur][prev] = T[prev][cur] ----------------
__global__ void prep_kernel(const float* __restrict__ trans) {
    int idx = blockIdx.x * 256 + threadIdx.x;     // 16384 total
    int p = idx >> 7, cu = idx & 127;
    g_Tt[cu * Csz + p] = trans[idx];
}

// ---------------- GEMM: emis = x @ W + b  (plain fp32, 128x128x16 tiles) ----------------
__global__ __launch_bounds__(256) void gemm_kernel(
    const float* __restrict__ x, const float* __restrict__ W,
    const float* __restrict__ bias)
{
    __shared__ float As[16][132];     // [k][m], padded
    __shared__ float Bs[16][128];     // [k][n]

    const int tid = threadIdx.x;
    const int tx = tid & 15;          // n group (8 cols)
    const int ty = tid >> 4;          // m group (8 rows)
    const size_t m_base = (size_t)blockIdx.x * 128;

    float acc[8][8];
    #pragma unroll
    for (int i = 0; i < 8; ++i)
        #pragma unroll
        for (int j = 0; j < 8; ++j) acc[i][j] = 0.0f;

    for (int kt = 0; kt < Dsz / 16; ++kt) {
        const int k0 = kt * 16;
        __syncthreads();              // previous tile reads complete before overwrite
        #pragma unroll
        for (int t = 0; t < 2; ++t) {                 // A: 512 float4
            int idx = tid + t * 256;
            int r = idx >> 2, q = idx & 3;
            float4 v = *(const float4*)(x + (m_base + r) * Dsz + k0 + q * 4);
            As[q * 4 + 0][r] = v.x; As[q * 4 + 1][r] = v.y;
            As[q * 4 + 2][r] = v.z; As[q * 4 + 3][r] = v.w;
        }
        #pragma unroll
        for (int t = 0; t < 2; ++t) {                 // B: 512 float4
            int idx = tid + t * 256;
            int r = idx >> 5, c = idx & 31;
            *(float4*)&Bs[r][c * 4] = *(const float4*)(W + (size_t)(k0 + r) * Csz + c * 4);
        }
        __syncthreads();
        #pragma unroll
        for (int k = 0; k < 16; ++k) {
            float a[8], bb[8];
            #pragma unroll
            for (int i = 0; i < 8; ++i) a[i] = As[k][ty * 8 + i];
            #pragma unroll
            for (int j = 0; j < 8; ++j) bb[j] = Bs[k][tx * 8 + j];
            #pragma unroll
            for (int i = 0; i < 8; ++i)
                #pragma unroll
                for (int j = 0; j < 8; ++j)
                    acc[i][j] = fmaf(a[i], bb[j], acc[i][j]);
        }
    }

    #pragma unroll
    for (int i = 0; i < 8; ++i) {
        float* orow = g_emis + (m_base + ty * 8 + i) * Csz + tx * 8;
        #pragma unroll
        for (int j = 0; j < 8; ++j)
            orow[j] = acc[i][j] + bias[tx * 8 + j];
    }
}

// ---------------- Viterbi forward: 1 CTA per batch, thread = cur state ----------------
// Stores entry-scores of every step (g_scores[b][l][*]) for exact backtrack recompute.
__global__ __launch_bounds__(128, 1) void forward_kernel(const float* __restrict__ trans)
{
    __shared__ __align__(16) float sbuf[264];   // two buffers, 132-float pitch
    const int b = blockIdx.x;
    const int c = threadIdx.x;
    const int len = g_len[b];

    float treg[128];                            // treg[p] = T[p][c]
    #pragma unroll
    for (int p = 0; p < 128; ++p) treg[p] = trans[p * Csz + c];

    float cur = 0.0f;
    const float* eptr = g_emis + (size_t)b * Lsz * Csz + c;
    float* scr = g_scores + (size_t)b * (Lsz + 1) * Csz + c;

    int par = 0;
    for (int l = 0; l < len; ++l) {
        float* sb = sbuf + (par ? 132 : 0);
        sb[c] = cur;
        scr[(size_t)l * Csz] = cur;             // entry scores of step l
        __syncthreads();
        float e = eptr[(size_t)l * Csz];
        float m0 = -3.4e38f, m1 = -3.4e38f, m2 = -3.4e38f, m3 = -3.4e38f;
        #pragma unroll
        for (int p = 0; p < 128; p += 4) {
            float4 ss = *(const float4*)(sb + p);
            m0 = fmaxf(m0, ss.x + treg[p + 0]);
            m1 = fmaxf(m1, ss.y + treg[p + 1]);
            m2 = fmaxf(m2, ss.z + treg[p + 2]);
            m3 = fmaxf(m3, ss.w + treg[p + 3]);
        }
        cur = fmaxf(fmaxf(m0, m1), fmaxf(m2, m3)) + e;
        par ^= 1;
    }
    scr[(size_t)len * Csz] = cur;               // final scores (pre STOP-transition)
}

// ---------------- backtrack: one warp per batch, shfl argmax (first index wins) ----------------
// NOTE: output buffer is float32 (harness __output__ dtype) — tags stored as floats.
__device__ __forceinline__ int warp_argmax(float v, int idx) {
    #pragma unroll
    for (int off = 16; off; off >>= 1) {
        float ov = __shfl_xor_sync(0xffffffffu, v, off);
        int   oi = __shfl_xor_sync(0xffffffffu, idx, off);
        if (ov > v || (ov == v && oi < idx)) { v = ov; idx = oi; }
    }
    return idx;
}

__global__ __launch_bounds__(32, 1) void backtrack_kernel(float* __restrict__ out)
{
    const int lane = threadIdx.x;
    const int b = blockIdx.x;
    const int len = g_len[b];
    const float* S = g_scores + (size_t)b * (Lsz + 1) * Csz;
    float* orow = out + (size_t)b * Lsz;
    const int i0 = lane * 4;

    // zero the padded tail (reference emits 0 past seq end)
    for (int l = len + lane; l < Lsz; l += 32) orow[l] = 0.0f;

    // last tag: argmax_c( final[c] + T[c][STOP] );  g_Tt[STOP][c] = T[c][STOP]
    float bv; int bi;
    {
        const float* fr = S + (size_t)len * Csz;
        const float* tr = g_Tt + STOPTAG * Csz;
        bv = fr[i0] + tr[i0]; bi = i0;
        #pragma unroll
        for (int q = 1; q < 4; ++q) {
            float v = fr[i0 + q] + tr[i0 + q];
            if (v > bv) { bv = v; bi = i0 + q; }
        }
    }
    int cur = warp_argmax(bv, bi);

    for (int l = len - 1; l >= 1; --l) {
        if (lane == 0) orow[l] = (float)cur;
        cur = __shfl_sync(0xffffffffu, cur, 0);
        const float* sr = S + (size_t)l * Csz;
        const float* tr = g_Tt + cur * Csz;
        bv = sr[i0] + tr[i0]; bi = i0;
        #pragma unroll
        for (int q = 1; q < 4; ++q) {
            float v = sr[i0 + q] + tr[i0 + q];
            if (v > bv) { bv = v; bi = i0 + q; }
        }
        cur = warp_argmax(bv, bi);
    }
    if (lane == 0) orow[0] = (float)cur;
}

// ---------------- launch ----------------
extern "C" void kernel_launch(void* const* d_in, const int* in_sizes, int n_in,
                              void* d_out, int out_size)
{
    const float* x = nullptr;
    const float* W = nullptr;
    const float* bias = nullptr;
    const float* trans = nullptr;
    const unsigned char* candA = nullptr;   // first 65536-elem input
    const unsigned char* candB = nullptr;   // second 65536-elem input
    for (int i = 0; i < n_in; ++i) {
        long long s = in_sizes[i];
        if      (s == (long long)Bsz * Lsz * Dsz) x = (const float*)d_in[i];
        else if (s == (long long)Dsz * Csz)       W = (const float*)d_in[i];
        else if (s == Csz)                        bias = (const float*)d_in[i];
        else if (s == Csz * Csz)                  trans = (const float*)d_in[i];
        else if (s == (long long)Bsz * Lsz) {
            if (!candA) candA = (const unsigned char*)d_in[i];
            else        candB = (const unsigned char*)d_in[i];
        }
    }
    float* out = (float*)d_out;

    detect_kernel<<<1, 256>>>(candA, candB);
    len_kernel<<<Bsz, 256>>>(candA, candB);
    prep_kernel<<<Csz * Csz / 256, 256>>>(trans);
    gemm_kernel<<<(Bsz * Lsz) / 128, 256>>>(x, W, bias);
    forward_kernel<<<Bsz, 128>>>(trans);
    backtrack_kernel<<<Bsz, 32>>>(out);
}

// round 7
// speedup vs baseline: 1.6861x; 1.6861x over previous
#include <cuda_runtime.h>
#include <cuda_bf16.h>

#define Bsz 64
#define Lsz 1024
#define Dsz 1024
#define Csz 128          // NUM_CLASS + 2
#define STOPTAG 127

// ---------------- scratch (device globals; no allocation allowed) ----------------
__device__ float g_emis[(size_t)Bsz * Lsz * Csz];            // 32 MB
__device__ float g_scores[(size_t)Bsz * (Lsz + 1) * Csz];    // 33.6 MB
__device__ float g_Tt[Csz * Csz];                            // 64 KB transposed T
__device__ int   g_len[Bsz];
__device__ int   g_sel;      // which 65536-elem candidate is the mask (0=A,1=B)
__device__ int   g_width;    // mask element storage width in bytes (1,4,8)

// ---------------- identify the mask among the two 65536-elem inputs ----------------
__global__ void detect_kernel(const unsigned char* A, const unsigned char* B) {
    __shared__ int bad[6];              // [cand*3 + w], w: 0=u64, 1=u32/f32, 2=u8
    int tid = threadIdx.x;
    if (tid < 6) bad[tid] = 0;
    __syncthreads();
    for (int cand = 0; cand < 2; ++cand) {
        const unsigned char* P = cand ? B : A;
        if (!P) { if (tid == 0) { bad[cand*3+0] = bad[cand*3+1] = bad[cand*3+2] = 1; } continue; }
        const unsigned long long* p8 = (const unsigned long long*)P;
        const unsigned* p4 = (const unsigned*)P;
        for (int i = tid; i < 1024; i += 256) {
            if (p8[i] > 1ull) atomicOr(&bad[cand*3+0], 1);
            unsigned v4 = p4[i];
            if (v4 != 0u && v4 != 1u && v4 != 0x3F800000u) atomicOr(&bad[cand*3+1], 1);
            if (P[i] > 1) atomicOr(&bad[cand*3+2], 1);
        }
    }
    __syncthreads();
    if (tid == 0) {
        int sel = 0, width = 1;
        bool done = false;
        for (int cand = 0; cand < 2 && !done; ++cand) {
            if      (!bad[cand*3+0]) { sel = cand; width = 8; done = true; }
            else if (!bad[cand*3+1]) { sel = cand; width = 4; done = true; }
            else if (!bad[cand*3+2]) { sel = cand; width = 1; done = true; }
        }
        g_sel = sel; g_width = width;
    }
}

// ---------------- sequence lengths: count nonzero per row at detected width ----------------
__global__ void len_kernel(const unsigned char* A, const unsigned char* B) {
    const unsigned char* M = g_sel ? B : A;
    const int w = g_width;
    const int b = blockIdx.x, tid = threadIdx.x;
    int cnt = 0;
    if (w == 8) {
        const unsigned long long* p = ((const unsigned long long*)M) + (size_t)b * Lsz;
        for (int i = tid; i < Lsz; i += 256) cnt += (p[i] != 0ull) ? 1 : 0;
    } else if (w == 4) {
        const unsigned* p = ((const unsigned*)M) + (size_t)b * Lsz;
        for (int i = tid; i < Lsz; i += 256) cnt += (p[i] != 0u) ? 1 : 0;
    } else {
        const unsigned char* p = M + (size_t)b * Lsz;
        for (int i = tid; i < Lsz; i += 256) cnt += (p[i] != 0) ? 1 : 0;
    }
    #pragma unroll
    for (int off = 16; off; off >>= 1) cnt += __shfl_xor_sync(0xffffffffu, cnt, off);
    __shared__ int sr[8];
    if ((tid & 31) == 0) sr[tid >> 5] = cnt;
    __syncthreads();
    if (tid == 0) {
        int s = 0;
        #pragma unroll
        for (int i = 0; i < 8; ++i) s += sr[i];
        g_len[b] = s;
    }
}

// ---------------- transpose T: g_Tt[cur][prev] = T[prev][cur] ----------------
__global__ void prep_kernel(const float* __restrict__ trans) {
    int idx = blockIdx.x * 256 + threadIdx.x;     // 16384 total
    int p = idx >> 7, cu = idx & 127;
    g_Tt[cu * Csz + p] = trans[idx];
}

// ---------------- GEMM: emis = x @ W + b  (fp32, packed f32x2 FFMA, double-buffered) ----------------
#define FMA2(d, a, b) asm("fma.rn.f32x2 %0, %1, %2, %0;" : "+l"(d) : "l"(a), "l"(b))
#define PACK2(d, s)   asm("mov.b64 %0, {%1, %1};" : "=l"(d) : "f"(s))
#define UNPACK2(lo, hi, s) asm("mov.b64 {%0, %1}, %2;" : "=f"(lo), "=f"(hi) : "l"(s))

__global__ __launch_bounds__(256, 2) void gemm_kernel(
    const float* __restrict__ x, const float* __restrict__ W,
    const float* __restrict__ bias)
{
    __shared__ __align__(16) float As[2][16][132];   // [k][m], padded (528B rows, 16B-aligned)
    __shared__ __align__(16) float Bs[2][16][128];   // [k][n]

    const int tid = threadIdx.x;
    const int tx = tid & 15;          // n group
    const int ty = tid >> 4;          // m group
    const size_t m_base = (size_t)blockIdx.x * 128;

    const int rA0 = tid >> 2,         qA0 = tid & 3;          // A: 512 float4
    const int rA1 = (tid + 256) >> 2, qA1 = tid & 3;
    const int rB0 = tid >> 5,         cB0 = tid & 31;         // B: 512 float4
    const int rB1 = (tid + 256) >> 5, cB1 = tid & 31;

    unsigned long long acc[4][8];
    #pragma unroll
    for (int i = 0; i < 4; ++i)
        #pragma unroll
        for (int j = 0; j < 8; ++j) acc[i][j] = 0ull;

    // ---- stage 0 ----
    {
        float4 va0 = *(const float4*)(x + (m_base + rA0) * Dsz + (qA0 << 2));
        float4 va1 = *(const float4*)(x + (m_base + rA1) * Dsz + (qA1 << 2));
        float4 vb0 = *(const float4*)(W + (size_t)rB0 * Csz + (cB0 << 2));
        float4 vb1 = *(const float4*)(W + (size_t)rB1 * Csz + (cB1 << 2));
        As[0][qA0 * 4 + 0][rA0] = va0.x; As[0][qA0 * 4 + 1][rA0] = va0.y;
        As[0][qA0 * 4 + 2][rA0] = va0.z; As[0][qA0 * 4 + 3][rA0] = va0.w;
        As[0][qA1 * 4 + 0][rA1] = va1.x; As[0][qA1 * 4 + 1][rA1] = va1.y;
        As[0][qA1 * 4 + 2][rA1] = va1.z; As[0][qA1 * 4 + 3][rA1] = va1.w;
        *(float4*)&Bs[0][rB0][cB0 << 2] = vb0;
        *(float4*)&Bs[0][rB1][cB1 << 2] = vb1;
    }
    __syncthreads();

    const int KT = Dsz / 16;   // 64
    float4 va0, va1, vb0, vb1;
    for (int kt = 0; kt < KT; ++kt) {
        const int buf = kt & 1;
        if (kt < KT - 1) {
            const int k0 = (kt + 1) * 16;
            va0 = *(const float4*)(x + (m_base + rA0) * Dsz + k0 + (qA0 << 2));
            va1 = *(const float4*)(x + (m_base + rA1) * Dsz + k0 + (qA1 << 2));
            vb0 = *(const float4*)(W + (size_t)(k0 + rB0) * Csz + (cB0 << 2));
            vb1 = *(const float4*)(W + (size_t)(k0 + rB1) * Csz + (cB1 << 2));
        }
        #pragma unroll
        for (int k = 0; k < 16; ++k) {
            const float* ap = &As[buf][k][ty * 8];
            ulonglong2 a01 = *(const ulonglong2*)ap;          // m-pairs packed
            ulonglong2 a23 = *(const ulonglong2*)(ap + 4);
            const float* bp = &Bs[buf][k][tx * 8];
            float4 b03 = *(const float4*)bp;
            float4 b47 = *(const float4*)(bp + 4);
            float bv[8] = {b03.x, b03.y, b03.z, b03.w, b47.x, b47.y, b47.z, b47.w};
            #pragma unroll
            for (int j = 0; j < 8; ++j) {
                unsigned long long bb;
                PACK2(bb, bv[j]);
                FMA2(acc[0][j], a01.x, bb);
                FMA2(acc[1][j], a01.y, bb);
                FMA2(acc[2][j], a23.x, bb);
                FMA2(acc[3][j], a23.y, bb);
            }
        }
        if (kt < KT - 1) {
            const int nb = buf ^ 1;
            __syncthreads();          // all reads of old buffer done before overwrite of nb? (nb untouched) -- needed to protect nb from early writers racing late readers of previous round
            As[nb][qA0 * 4 + 0][rA0] = va0.x; As[nb][qA0 * 4 + 1][rA0] = va0.y;
            As[nb][qA0 * 4 + 2][rA0] = va0.z; As[nb][qA0 * 4 + 3][rA0] = va0.w;
            As[nb][qA1 * 4 + 0][rA1] = va1.x; As[nb][qA1 * 4 + 1][rA1] = va1.y;
            As[nb][qA1 * 4 + 2][rA1] = va1.z; As[nb][qA1 * 4 + 3][rA1] = va1.w;
            *(float4*)&Bs[nb][rB0][cB0 << 2] = vb0;
            *(float4*)&Bs[nb][rB1][cB1 << 2] = vb1;
            __syncthreads();
        }
    }

    float bvv[8];
    #pragma unroll
    for (int j = 0; j < 8; ++j) bvv[j] = bias[tx * 8 + j];
    #pragma unroll
    for (int i = 0; i < 4; ++i) {
        float lo[8], hi[8];
        #pragma unroll
        for (int j = 0; j < 8; ++j) {
            UNPACK2(lo[j], hi[j], acc[i][j]);
            lo[j] += bvv[j]; hi[j] += bvv[j];
        }
        size_t me = m_base + ty * 8 + 2 * i;
        float* oe = g_emis + me * Csz + tx * 8;
        float* oo = g_emis + (me + 1) * Csz + tx * 8;
        *(float4*)oe       = make_float4(lo[0], lo[1], lo[2], lo[3]);
        *(float4*)(oe + 4) = make_float4(lo[4], lo[5], lo[6], lo[7]);
        *(float4*)oo       = make_float4(hi[0], hi[1], hi[2], hi[3]);
        *(float4*)(oo + 4) = make_float4(hi[4], hi[5], hi[6], hi[7]);
    }
}

// ---------------- Viterbi forward: 1 CTA per batch, thread = cur state ----------------
__global__ __launch_bounds__(128, 1) void forward_kernel(const float* __restrict__ trans)
{
    __shared__ __align__(16) float sbuf[264];   // two buffers, 132-float pitch
    const int b = blockIdx.x;
    const int c = threadIdx.x;
    const int len = g_len[b];

    float treg[128];                            // treg[p] = T[p][c]
    #pragma unroll
    for (int p = 0; p < 128; ++p) treg[p] = trans[p * Csz + c];

    float cur = 0.0f;
    const float* eptr = g_emis + (size_t)b * Lsz * Csz + c;
    float* scr = g_scores + (size_t)b * (Lsz + 1) * Csz + c;

    float e_next = eptr[0];                     // prefetch step-0 emission
    int par = 0;
    for (int l = 0; l < len; ++l) {
        float* sb = sbuf + (par ? 132 : 0);
        sb[c] = cur;
        scr[(size_t)l * Csz] = cur;             // entry scores of step l
        __syncthreads();
        float e = e_next;
        if (l + 1 < len) e_next = eptr[(size_t)(l + 1) * Csz];   // hide L2 latency behind math
        float m0 = -3.4e38f, m1 = -3.4e38f, m2 = -3.4e38f, m3 = -3.4e38f;
        #pragma unroll
        for (int p = 0; p < 128; p += 4) {
            float4 ss = *(const float4*)(sb + p);
            m0 = fmaxf(m0, ss.x + treg[p + 0]);
            m1 = fmaxf(m1, ss.y + treg[p + 1]);
            m2 = fmaxf(m2, ss.z + treg[p + 2]);
            m3 = fmaxf(m3, ss.w + treg[p + 3]);
        }
        cur = fmaxf(fmaxf(m0, m1), fmaxf(m2, m3)) + e;
        par ^= 1;
    }
    scr[(size_t)len * Csz] = cur;               // final scores (pre STOP-transition)
}

// ---------------- backtrack: 8 warps/CTA share smem Tt; redux argmax ----------------
__device__ __forceinline__ unsigned orderable(float f) {
    unsigned u = __float_as_uint(f);
    return (u & 0x80000000u) ? ~u : (u | 0x80000000u);
}

// lanes hold (local best value, local first index); returns global first-occurrence argmax
__device__ __forceinline__ int warp_argmax_redux(float bv, int bi) {
    unsigned u = orderable(bv);
    unsigned mx = __reduce_max_sync(0xffffffffu, u);
    unsigned cand = (u == mx) ? (unsigned)bi : 0xffffffffu;
    return (int)__reduce_min_sync(0xffffffffu, cand);
}

__global__ __launch_bounds__(256, 1) void backtrack_kernel(float* __restrict__ out)
{
    extern __shared__ __align__(16) float Tt[];   // [128][128] = 64 KB
    const int tid = threadIdx.x;
    for (int idx = tid; idx < 128 * 128; idx += 256) {
        int p = idx >> 7, cu = idx & 127;
        Tt[cu * Csz + p] = __ldg(&g_Tt[0]) * 0.0f + 0.0f;  // placeholder avoided below
    }
    // real fill (transposed copy already materialized in g_Tt by prep_kernel)
    for (int idx = tid; idx < 128 * 128; idx += 256) Tt[idx] = g_Tt[idx];
    __syncthreads();

    const int w = tid >> 5, lane = tid & 31;
    const int b = blockIdx.x * 8 + w;
    const int len = g_len[b];
    const float* S = g_scores + (size_t)b * (Lsz + 1) * Csz;
    float* orow = out + (size_t)b * Lsz;
    const int i0 = lane * 4;

    // zero the padded tail (reference emits 0 past seq end)
    for (int l = len + lane; l < Lsz; l += 32) orow[l] = 0.0f;

    // last tag: argmax_c( final[c] + T[c][STOP] );  Tt[STOP][c] = T[c][STOP]
    float4 fv = *(const float4*)(S + (size_t)len * Csz + i0);
    float4 tv = *(const float4*)(Tt + STOPTAG * Csz + i0);
    float bv; int bi;
    {
        float v0 = fv.x + tv.x, v1 = fv.y + tv.y, v2 = fv.z + tv.z, v3 = fv.w + tv.w;
        bv = v0; bi = i0;
        if (v1 > bv) { bv = v1; bi = i0 + 1; }
        if (v2 > bv) { bv = v2; bi = i0 + 2; }
        if (v3 > bv) { bv = v3; bi = i0 + 3; }
    }
    int cur = warp_argmax_redux(bv, bi);

    // reverse walk; prefetch next score row (address independent of cur)
    float4 r = *(const float4*)(S + (size_t)(len - 1) * Csz + i0);
    for (int l = len - 1; l >= 1; --l) {
        float4 rn;
        if (l > 1) rn = *(const float4*)(S + (size_t)(l - 1) * Csz + i0);
        if (lane == 0) orow[l] = (float)cur;
        float4 t = *(const float4*)(Tt + cur * Csz + i0);     // 29-cyc LDS, was ~250-cyc L2
        float v0 = r.x + t.x, v1 = r.y + t.y, v2 = r.z + t.z, v3 = r.w + t.w;
        bv = v0; bi = i0;
        if (v1 > bv) { bv = v1; bi = i0 + 1; }
        if (v2 > bv) { bv = v2; bi = i0 + 2; }
        if (v3 > bv) { bv = v3; bi = i0 + 3; }
        cur = warp_argmax_redux(bv, bi);
        if (l > 1) r = rn;
    }
    if (lane == 0) orow[0] = (float)cur;
}

// ---------------- launch ----------------
extern "C" void kernel_launch(void* const* d_in, const int* in_sizes, int n_in,
                              void* d_out, int out_size)
{
    const float* x = nullptr;
    const float* W = nullptr;
    const float* bias = nullptr;
    const float* trans = nullptr;
    const unsigned char* candA = nullptr;
    const unsigned char* candB = nullptr;
    for (int i = 0; i < n_in; ++i) {
        long long s = in_sizes[i];
        if      (s == (long long)Bsz * Lsz * Dsz) x = (const float*)d_in[i];
        else if (s == (long long)Dsz * Csz)       W = (const float*)d_in[i];
        else if (s == Csz)                        bias = (const float*)d_in[i];
        else if (s == Csz * Csz)                  trans = (const float*)d_in[i];
        else if (s == (long long)Bsz * Lsz) {
            if (!candA) candA = (const unsigned char*)d_in[i];
            else        candB = (const unsigned char*)d_in[i];
        }
    }
    float* out = (float*)d_out;

    static int smem_set = 0;
    if (!smem_set) {
        cudaFuncSetAttribute(backtrack_kernel,
                             cudaFuncAttributeMaxDynamicSharedMemorySize, 128 * 128 * 4);
        smem_set = 1;
    }

    detect_kernel<<<1, 256>>>(candA, candB);
    len_kernel<<<Bsz, 256>>>(candA, candB);
    prep_kernel<<<Csz * Csz / 256, 256>>>(trans);
    gemm_kernel<<<(Bsz * Lsz) / 128, 256>>>(x, W, bias);
    forward_kernel<<<Bsz, 128>>>(trans);
    backtrack_kernel<<<Bsz / 8, 256, 128 * 128 * 4>>>(out);
}